// round 1
// baseline (speedup 1.0000x reference)
#include <cuda_runtime.h>

// Problem shape (fixed by the dataset reference)
#define BB    16
#define TT    256
#define NPTS  2048
#define TCHUNK 64
#define NCHUNKS (TT / TCHUNK)
#define THREADS 256

// Per-point stats layout (stat * NPTS + n):
//  0..2  : sum m*pred_c          3..5 : sum m*pred_c^2
//  6..8  : sum m*gt_c            9..11: sum m*gt_c^2
//  12    : count (sum m)
__device__ float g_stats[13 * NPTS];
// 0: num_visible  1: recon_sum  2: vel_sq_sum  3: vel_count
__device__ float g_scal[4];

__global__ void zero_k() {
    int i = blockIdx.x * blockDim.x + threadIdx.x;
    if (i < 13 * NPTS) g_stats[i] = 0.0f;
    if (i < 4)         g_scal[i] = 0.0f;
}

__global__ __launch_bounds__(THREADS) void main_k(
    const float* __restrict__ pred,
    const float* __restrict__ gt,
    const float* __restrict__ vis)
{
    int tid   = blockIdx.x * THREADS + threadIdx.x;
    int n     = tid & (NPTS - 1);      // NPTS = 2^11
    int bc    = tid >> 11;             // b * NCHUNKS + chunk
    int chunk = bc % NCHUNKS;
    int b     = bc / NCHUNKS;
    int t0    = chunk * TCHUNK;

    float sxp0=0.f,sxp1=0.f,sxp2=0.f, ssp0=0.f,ssp1=0.f,ssp2=0.f;
    float sxg0=0.f,sxg1=0.f,sxg2=0.f, ssg0=0.f,ssg1=0.f,ssg2=0.f;
    float cnt=0.f, recon=0.f, vels=0.f, velc=0.f;

    // previous-frame state for velocity (register carried)
    float ppx=0.f,ppy=0.f,ppz=0.f, pgx=0.f,pgy=0.f,pgz=0.f, pm=0.f;
    if (t0 > 0) {
        int vi = (b * TT + (t0 - 1)) * NPTS + n;
        int pi = vi * 3;
        pm  = (vis[vi] > 0.5f) ? 1.f : 0.f;
        ppx = pred[pi]; ppy = pred[pi + 1]; ppz = pred[pi + 2];
        pgx = gt[pi];   pgy = gt[pi + 1];   pgz = gt[pi + 2];
    }

#pragma unroll 4
    for (int t = t0; t < t0 + TCHUNK; ++t) {
        int vi = (b * TT + t) * NPTS + n;
        int pi = vi * 3;
        float m  = (vis[vi] > 0.5f) ? 1.f : 0.f;
        float px = pred[pi], py = pred[pi + 1], pz = pred[pi + 2];
        float gx = gt[pi],   gy = gt[pi + 1],   gz = gt[pi + 2];

        // reconstruction: coord-weighted masked MSE (z weighted 2x)
        float dx = px - gx, dy = py - gy, dz = pz - gz;
        recon += m * (dx * dx + dy * dy + 2.f * dz * dz);
        cnt   += m;

        // identity: masked running sums and sum-of-squares
        float mpx = m * px, mpy = m * py, mpz = m * pz;
        float mgx = m * gx, mgy = m * gy, mgz = m * gz;
        sxp0 += mpx; sxp1 += mpy; sxp2 += mpz;
        ssp0 += mpx * px; ssp1 += mpy * py; ssp2 += mpz * pz;
        sxg0 += mgx; sxg1 += mgy; sxg2 += mgz;
        ssg0 += mgx * gx; ssg1 += mgy * gy; ssg2 += mgz * gz;

        // temporal: masked velocity MSE
        float vm = m * pm;
        float vx = (px - ppx) - (gx - pgx);
        float vy = (py - ppy) - (gy - pgy);
        float vz = (pz - ppz) - (gz - pgz);
        vels += vm * (vx * vx + vy * vy + vz * vz);
        velc += vm;

        ppx = px; ppy = py; ppz = pz;
        pgx = gx; pgy = gy; pgz = gz;
        pm  = m;
    }

    // per-point stats -> global scratch (coalesced REDG, contenders = B*NCHUNKS = 64)
    atomicAdd(&g_stats[ 0 * NPTS + n], sxp0);
    atomicAdd(&g_stats[ 1 * NPTS + n], sxp1);
    atomicAdd(&g_stats[ 2 * NPTS + n], sxp2);
    atomicAdd(&g_stats[ 3 * NPTS + n], ssp0);
    atomicAdd(&g_stats[ 4 * NPTS + n], ssp1);
    atomicAdd(&g_stats[ 5 * NPTS + n], ssp2);
    atomicAdd(&g_stats[ 6 * NPTS + n], sxg0);
    atomicAdd(&g_stats[ 7 * NPTS + n], sxg1);
    atomicAdd(&g_stats[ 8 * NPTS + n], sxg2);
    atomicAdd(&g_stats[ 9 * NPTS + n], ssg0);
    atomicAdd(&g_stats[10 * NPTS + n], ssg1);
    atomicAdd(&g_stats[11 * NPTS + n], ssg2);
    atomicAdd(&g_stats[12 * NPTS + n], cnt);

    // scalar losses: warp-reduce then one atomic per warp
    unsigned fmask = 0xffffffffu;
#pragma unroll
    for (int o = 16; o > 0; o >>= 1) {
        cnt   += __shfl_down_sync(fmask, cnt,   o);
        recon += __shfl_down_sync(fmask, recon, o);
        vels  += __shfl_down_sync(fmask, vels,  o);
        velc  += __shfl_down_sync(fmask, velc,  o);
    }
    if ((threadIdx.x & 31) == 0) {
        atomicAdd(&g_scal[0], cnt);
        atomicAdd(&g_scal[1], recon);
        atomicAdd(&g_scal[2], vels);
        atomicAdd(&g_scal[3], velc);
    }
}

__global__ __launch_bounds__(1024) void final_k(float* __restrict__ out) {
    __shared__ float red[1024];
    int tid = threadIdx.x;

    float local = 0.f;
    for (int n = tid; n < NPTS; n += 1024) {
        float c = g_stats[12 * NPTS + n];
        if (c > 1.f) {
            float inv_n  = 1.f / c;
            float inv_n1 = 1.f / (c - 1.f);
            float adsum = 0.f, vgsum = 0.f;
#pragma unroll
            for (int k = 0; k < 3; ++k) {
                float sp  = g_stats[(0 + k) * NPTS + n];
                float ssp = g_stats[(3 + k) * NPTS + n];
                float sg  = g_stats[(6 + k) * NPTS + n];
                float ssg = g_stats[(9 + k) * NPTS + n];
                float vp = (ssp - sp * sp * inv_n) * inv_n1;
                float vg = (ssg - sg * sg * inv_n) * inv_n1;
                adsum += fabsf(vp - vg);
                vgsum += vg;
            }
            local += adsum / (vgsum + 1e-6f);
        }
    }
    red[tid] = local;
    __syncthreads();
#pragma unroll
    for (int s = 512; s > 0; s >>= 1) {
        if (tid < s) red[tid] += red[tid + s];
        __syncthreads();
    }

    if (tid == 0) {
        float identity = red[0] / (float)NPTS;
        float nv = g_scal[0], rs = g_scal[1], vs = g_scal[2], vc = g_scal[3];
        float recon    = (nv > 0.f) ? rs / fmaxf(nv, 1.f) : 0.f;
        float temporal = (vc > 0.f) ? vs / fmaxf(vc, 1.f) : 0.f;

        // adaptive re-weighting (faithful to reference; branch can never fire
        // since comp <= max < (10/3)*max, but kept for exactness)
        float rl = recon, tl = temporal, il = identity;
        bool  all_pos = (rl > 0.f) && (tl > 0.f) && (il > 0.f);
        float maxc    = fmaxf(rl, fmaxf(tl, il));
        float target  = maxc / 3.f;
        float thresh  = 10.f * target;
        float rw = (all_pos && rl > thresh) ? 1.0f * target / fmaxf(rl, 1e-30f) : 1.0f;
        float tw = (all_pos && tl > thresh) ? 0.5f * target / fmaxf(tl, 1e-30f) : 0.5f;
        float iw = (all_pos && il > thresh) ? 0.1f * target / fmaxf(il, 1e-30f) : 0.1f;

        out[0] = rw * recon + tw * temporal + iw * identity;
        out[1] = recon;
        out[2] = temporal;
        out[3] = identity;
    }
}

extern "C" void kernel_launch(void* const* d_in, const int* in_sizes, int n_in,
                              void* d_out, int out_size)
{
    const float* pred = (const float*)d_in[0];
    const float* gt   = (const float*)d_in[1];
    const float* vis  = (const float*)d_in[2];
    float* out = (float*)d_out;

    (void)in_sizes; (void)n_in; (void)out_size;

    int zgrid = (13 * NPTS + THREADS - 1) / THREADS;
    zero_k<<<zgrid, THREADS>>>();

    int mgrid = (BB * NCHUNKS * NPTS) / THREADS;  // 512 blocks
    main_k<<<mgrid, THREADS>>>(pred, gt, vis);

    final_k<<<1, 1024>>>(out);
}